// round 13
// baseline (speedup 1.0000x reference)
#include <cuda_runtime.h>
#include <cuda_bf16.h>
#include <cuda_fp16.h>
#include <cstdint>

#define T_STEPS 5
#define NN 100000
#define DD 64
#define EE 400000

#define M_TOT (T_STEPS * NN)            // 500000 (t,node) rows
#define CHUNK 1024
#define NCHUNK ((M_TOT + CHUNK - 1) / CHUNK)  // 489

// ---------------- device scratch (static globals: allocation-free) ----------
__device__ float  g_A[(size_t)T_STEPS * NN * DD];   // x @ W_top  (128 MB, fp32)
__device__ __half g_Bh[(size_t)T_STEPS * NN * DD];  // x @ W_bot  (64 MB, fp16)
__device__ __nv_bfloat16 g_xh[(size_t)NN * DD];     // x hi split
__device__ __nv_bfloat16 g_xl[(size_t)NN * DD];     // x lo split
__device__ __nv_bfloat16 g_wh[(size_t)T_STEPS * 128 * 64];  // W hi, [t][j][k]
__device__ __nv_bfloat16 g_wl[(size_t)T_STEPS * 128 * 64];  // W lo, [t][j][k]
__device__ int   g_cnt[M_TOT];
__device__ int   g_rowptr[M_TOT];
__device__ int   g_cursor[M_TOT];
__device__ int   g_sdst[(size_t)T_STEPS * EE];      // dst sorted by (t,src)
__device__ int   g_chunksum[NCHUNK];
__device__ int   g_chunkoff[NCHUNK];
__device__ float g_w[T_STEPS];

// ---------------- helpers ----------------------------------------------------
__device__ __forceinline__ uint32_t pack_bf2(__nv_bfloat16 a, __nv_bfloat16 b) {
    __nv_bfloat162 p = __halves2bfloat162(a, b);
    return *(uint32_t*)&p;
}

__device__ __forceinline__ void mma_bf16(float* c, const uint32_t* a,
                                         uint32_t b0, uint32_t b1) {
    asm("mma.sync.aligned.m16n8k16.row.col.f32.bf16.bf16.f32 "
        "{%0,%1,%2,%3}, {%4,%5,%6,%7}, {%8,%9}, {%0,%1,%2,%3};"
        : "+f"(c[0]), "+f"(c[1]), "+f"(c[2]), "+f"(c[3])
        : "r"(a[0]), "r"(a[1]), "r"(a[2]), "r"(a[3]), "r"(b0), "r"(b1));
}

// ---------------- fused split kernel (x and W halves by block range) --------
#define XSPLIT_BLOCKS 6250   // NN*DD/4 / 256
#define WSPLIT_BLOCKS 160    // T*128*64 / 256
__global__ void k_split_xw(const float* __restrict__ x,
                           const float* __restrict__ W) {
    int b = blockIdx.x;
    if (b < XSPLIT_BLOCKS) {
        int i = b * 256 + threadIdx.x;
        if (i >= NN * DD / 4) return;
        float4 v = ((const float4*)x)[i];
        __nv_bfloat16 h0 = __float2bfloat16(v.x);
        __nv_bfloat16 h1 = __float2bfloat16(v.y);
        __nv_bfloat16 h2 = __float2bfloat16(v.z);
        __nv_bfloat16 h3 = __float2bfloat16(v.w);
        __nv_bfloat16 l0 = __float2bfloat16(v.x - __bfloat162float(h0));
        __nv_bfloat16 l1 = __float2bfloat16(v.y - __bfloat162float(h1));
        __nv_bfloat16 l2 = __float2bfloat16(v.z - __bfloat162float(h2));
        __nv_bfloat16 l3 = __float2bfloat16(v.w - __bfloat162float(h3));
        ((uint2*)g_xh)[i] = make_uint2(pack_bf2(h0, h1), pack_bf2(h2, h3));
        ((uint2*)g_xl)[i] = make_uint2(pack_bf2(l0, l1), pack_bf2(l2, l3));
    } else {
        int i = (b - XSPLIT_BLOCKS) * 256 + threadIdx.x;
        if (i >= T_STEPS * 128 * 64) return;
        int t = i >> 13;
        int j = (i >> 6) & 127;
        int k = i & 63;
        int kcat = k + ((j >> 6) << 6);
        float v = W[(size_t)t * 8192 + kcat * 64 + (j & 63)];
        __nv_bfloat16 h = __float2bfloat16(v);
        __nv_bfloat16 l = __float2bfloat16(v - __bfloat162float(h));
        g_wh[i] = h;
        g_wl[i] = l;
    }
}

// ---------------- tiny kernels ---------------------------------------------
__global__ void k_zero_cnt() {
    int i = blockIdx.x * blockDim.x + threadIdx.x;
    if (i < M_TOT) g_cnt[i] = 0;
}

__global__ void k_softmax(const float* __restrict__ ea) {
    if (threadIdx.x == 0) {
        float m = ea[0];
        for (int t = 1; t < T_STEPS; t++) m = fmaxf(m, ea[t]);
        float s = 0.f, e[T_STEPS];
        for (int t = 0; t < T_STEPS; t++) { e[t] = __expf(ea[t] - m); s += e[t]; }
        for (int t = 0; t < T_STEPS; t++) g_w[t] = e[t] / s;
    }
}

__global__ void k_hist(const int* __restrict__ edges) {
    int i = blockIdx.x * blockDim.x + threadIdx.x;
    if (i >= T_STEPS * EE) return;
    int t = i / EE, e = i - t * EE;
    int src = edges[(size_t)t * 2 * EE + e];
    atomicAdd(&g_cnt[t * NN + src], 1);
}

__global__ void k_scan1() {
    __shared__ int sh[256];
    int c = blockIdx.x, tid = threadIdx.x;
    int base = c * CHUNK;
    int s = 0;
    #pragma unroll
    for (int i = 0; i < CHUNK / 256; i++) {
        int idx = base + i * 256 + tid;
        if (idx < M_TOT) s += g_cnt[idx];
    }
    sh[tid] = s; __syncthreads();
    for (int off = 128; off > 0; off >>= 1) {
        if (tid < off) sh[tid] += sh[tid + off];
        __syncthreads();
    }
    if (tid == 0) g_chunksum[c] = sh[0];
}

// single-block parallel exclusive scan over NCHUNK chunk sums (512 threads)
__global__ void k_scan2() {
    __shared__ int sh[512];
    int tid = threadIdx.x;
    int v = (tid < NCHUNK) ? g_chunksum[tid] : 0;
    sh[tid] = v; __syncthreads();
    for (int off = 1; off < 512; off <<= 1) {
        int add = (tid >= off) ? sh[tid - off] : 0;
        __syncthreads();
        sh[tid] += add;
        __syncthreads();
    }
    if (tid < NCHUNK) g_chunkoff[tid] = sh[tid] - v;
}

__global__ void k_scan3() {
    __shared__ int sh[256];
    int c = blockIdx.x, tid = threadIdx.x;
    const int PT = CHUNK / 256;  // 4
    int base = c * CHUNK + tid * PT;
    int v[PT];
    int s = 0;
    #pragma unroll
    for (int i = 0; i < PT; i++) {
        int idx = base + i;
        int cv = (idx < M_TOT) ? g_cnt[idx] : 0;
        v[i] = s; s += cv;
    }
    sh[tid] = s; __syncthreads();
    for (int off = 1; off < 256; off <<= 1) {
        int add = (tid >= off) ? sh[tid - off] : 0;
        __syncthreads();
        sh[tid] += add;
        __syncthreads();
    }
    int texcl = ((tid > 0) ? sh[tid - 1] : 0) + g_chunkoff[c];
    #pragma unroll
    for (int i = 0; i < PT; i++) {
        int idx = base + i;
        if (idx < M_TOT) {
            int o = texcl + v[i];
            g_rowptr[idx] = o;
            g_cursor[idx] = o;
        }
    }
}

__global__ void k_scatter(const int* __restrict__ edges) {
    int i = blockIdx.x * blockDim.x + threadIdx.x;
    if (i >= T_STEPS * EE) return;
    int t = i / EE, e = i - t * EE;
    int src = edges[(size_t)t * 2 * EE + e];
    int dst = edges[(size_t)t * 2 * EE + EE + e];
    int pos = atomicAdd(&g_cursor[t * NN + src], 1);
    g_sdst[pos] = dst;
}

// ---------------- GEMM via split-bf16 tensor cores --------------------------
// A half (j<64) -> g_A fp32 ; B half (j>=64) -> g_Bh fp16.
#define BS 72
__global__ void __launch_bounds__(256) k_gemm() {
    extern __shared__ __nv_bfloat16 smem[];
    __nv_bfloat16* xh_s = smem;                  // [128][BS]
    __nv_bfloat16* xl_s = smem + 128 * BS;
    __nv_bfloat16* wh_s = smem + 2 * 128 * BS;   // [128 j][BS k]
    __nv_bfloat16* wl_s = smem + 3 * 128 * BS;

    int t   = blockIdx.y;
    int n0  = blockIdx.x * 128;
    int tid = threadIdx.x;

    #pragma unroll
    for (int j = 0; j < 4; j++) {
        int idx = tid + j * 256;
        int nl = idx >> 3, kq = idx & 7;
        int n = n0 + nl;
        uint4 hv = make_uint4(0, 0, 0, 0), lv = make_uint4(0, 0, 0, 0);
        if (n < NN) {
            hv = ((const uint4*)g_xh)[((size_t)n * 64 >> 3) + kq];
            lv = ((const uint4*)g_xl)[((size_t)n * 64 >> 3) + kq];
        }
        ((uint4*)xh_s)[nl * 9 + kq] = hv;
        ((uint4*)xl_s)[nl * 9 + kq] = lv;
    }
    const uint4* whg = (const uint4*)(g_wh + (size_t)t * 8192);
    const uint4* wlg = (const uint4*)(g_wl + (size_t)t * 8192);
    #pragma unroll
    for (int j = 0; j < 4; j++) {
        int idx = tid + j * 256;
        int jr = idx >> 3, kq = idx & 7;
        ((uint4*)wh_s)[jr * 9 + kq] = whg[idx];
        ((uint4*)wl_s)[jr * 9 + kq] = wlg[idx];
    }
    __syncthreads();

    int wid = tid >> 5, lane = tid & 31;
    int warp_m = wid & 3, warp_n = wid >> 2;
    int g = lane >> 2, tg = lane & 3;

    float acc[2][8][4];
    #pragma unroll
    for (int mf = 0; mf < 2; mf++)
        #pragma unroll
        for (int nf = 0; nf < 8; nf++)
            #pragma unroll
            for (int r = 0; r < 4; r++) acc[mf][nf][r] = 0.f;

    #pragma unroll
    for (int ks = 0; ks < 4; ks++) {
        int kk = ks * 16;
        uint32_t ah[2][4], al[2][4];
        #pragma unroll
        for (int mf = 0; mf < 2; mf++) {
            int r0 = warp_m * 32 + mf * 16 + g;
            int k0 = kk + 2 * tg;
            ah[mf][0] = *(const uint32_t*)&xh_s[r0 * BS + k0];
            ah[mf][1] = *(const uint32_t*)&xh_s[(r0 + 8) * BS + k0];
            ah[mf][2] = *(const uint32_t*)&xh_s[r0 * BS + k0 + 8];
            ah[mf][3] = *(const uint32_t*)&xh_s[(r0 + 8) * BS + k0 + 8];
            al[mf][0] = *(const uint32_t*)&xl_s[r0 * BS + k0];
            al[mf][1] = *(const uint32_t*)&xl_s[(r0 + 8) * BS + k0];
            al[mf][2] = *(const uint32_t*)&xl_s[r0 * BS + k0 + 8];
            al[mf][3] = *(const uint32_t*)&xl_s[(r0 + 8) * BS + k0 + 8];
        }
        #pragma unroll
        for (int nf = 0; nf < 8; nf++) {
            int col = warp_n * 64 + nf * 8 + g;
            int k0 = kk + 2 * tg;
            uint32_t bh0 = *(const uint32_t*)&wh_s[col * BS + k0];
            uint32_t bh1 = *(const uint32_t*)&wh_s[col * BS + k0 + 8];
            uint32_t bl0 = *(const uint32_t*)&wl_s[col * BS + k0];
            uint32_t bl1 = *(const uint32_t*)&wl_s[col * BS + k0 + 8];
            #pragma unroll
            for (int mf = 0; mf < 2; mf++) {
                mma_bf16(acc[mf][nf], ah[mf], bh0, bh1);
                mma_bf16(acc[mf][nf], ah[mf], bl0, bl1);
                mma_bf16(acc[mf][nf], al[mf], bh0, bh1);
            }
        }
    }

    // epilogue: warp_n==0 -> g_A (fp32), warp_n==1 -> g_Bh (fp16)
    #pragma unroll
    for (int mf = 0; mf < 2; mf++) {
        int rb = warp_m * 32 + mf * 16;
        int nA = n0 + rb + g;
        int nB = n0 + rb + g + 8;
        #pragma unroll
        for (int nf = 0; nf < 8; nf++) {
            int jc = nf * 8 + 2 * tg;
            if (warp_n == 0) {
                if (nA < NN) {
                    float2 v = make_float2(acc[mf][nf][0], acc[mf][nf][1]);
                    *(float2*)&g_A[((size_t)t * NN + nA) * 64 + jc] = v;
                }
                if (nB < NN) {
                    float2 v = make_float2(acc[mf][nf][2], acc[mf][nf][3]);
                    *(float2*)&g_A[((size_t)t * NN + nB) * 64 + jc] = v;
                }
            } else {
                if (nA < NN) {
                    __half2 v = __floats2half2_rn(acc[mf][nf][0], acc[mf][nf][1]);
                    *(__half2*)&g_Bh[((size_t)t * NN + nA) * 64 + jc] = v;
                }
                if (nB < NN) {
                    __half2 v = __floats2half2_rn(acc[mf][nf][2], acc[mf][nf][3]);
                    *(__half2*)&g_Bh[((size_t)t * NN + nB) * 64 + jc] = v;
                }
            }
        }
    }
}

// ---------------- finalize: one warp per node, fp16 B gathers ---------------
__global__ void k_finalize(const float* __restrict__ bias,
                           float* __restrict__ out) {
    int gw = (blockIdx.x * blockDim.x + threadIdx.x) >> 5;
    int lane = threadIdx.x & 31;
    if (gw >= NN) return;
    int n = gw;

    int beg[T_STEPS], cnt[T_STEPS];
    #pragma unroll
    for (int t = 0; t < T_STEPS; t++) {
        int row = t * NN + n;
        beg[t] = g_rowptr[row];
        cnt[t] = g_cnt[row];
    }
    int dv[T_STEPS];
    #pragma unroll
    for (int t = 0; t < T_STEPS; t++)
        dv[t] = (lane < cnt[t]) ? g_sdst[beg[t] + lane] : 0;
    float2 av[T_STEPS];
    #pragma unroll
    for (int t = 0; t < T_STEPS; t++)
        av[t] = *(const float2*)&g_A[((size_t)(t * NN + n)) * 64 + 2 * lane];

    float ox = 0.f, oy = 0.f;

    #pragma unroll
    for (int t = 0; t < T_STEPS; t++) {
        float2 bi = *(const float2*)&bias[t * 64 + 2 * lane];
        float ax = av[t].x + bi.x, ay = av[t].y + bi.y;
        // B row = 64 halves = 32 half2; lane reads half2 at [d*32 + lane]
        const __half2* Bt = (const __half2*)(g_Bh + (size_t)t * NN * 64);

        float sx = 0.f, sy = 0.f;
        int c = cnt[t];
        int m = min(32, c);
        int i = 0;
        for (; i + 8 <= m; i += 8) {
            float2 bv[8];
            #pragma unroll
            for (int q = 0; q < 8; q++) {
                int dq = __shfl_sync(0xffffffffu, dv[t], i + q);
                bv[q] = __half22float2(Bt[(size_t)dq * 32 + lane]);
            }
            #pragma unroll
            for (int q = 0; q < 8; q++) {
                sx += fmaxf(ax + bv[q].x, 0.f);
                sy += fmaxf(ay + bv[q].y, 0.f);
            }
        }
        if (i + 4 <= m) {
            float2 bv[4];
            #pragma unroll
            for (int q = 0; q < 4; q++) {
                int dq = __shfl_sync(0xffffffffu, dv[t], i + q);
                bv[q] = __half22float2(Bt[(size_t)dq * 32 + lane]);
            }
            #pragma unroll
            for (int q = 0; q < 4; q++) {
                sx += fmaxf(ax + bv[q].x, 0.f);
                sy += fmaxf(ay + bv[q].y, 0.f);
            }
            i += 4;
        }
        for (; i < m; i++) {
            int di = __shfl_sync(0xffffffffu, dv[t], i);
            float2 bv = __half22float2(Bt[(size_t)di * 32 + lane]);
            sx += fmaxf(ax + bv.x, 0.f);
            sy += fmaxf(ay + bv.y, 0.f);
        }
        // rare tail: degree > 32
        for (int base = 32; base < c; base += 32) {
            int mm = min(32, c - base);
            int d = (lane < mm) ? g_sdst[beg[t] + base + lane] : 0;
            int ii = 0;
            for (; ii + 4 <= mm; ii += 4) {
                float2 b0 = __half22float2(Bt[(size_t)__shfl_sync(0xffffffffu, d, ii)     * 32 + lane]);
                float2 b1 = __half22float2(Bt[(size_t)__shfl_sync(0xffffffffu, d, ii + 1) * 32 + lane]);
                float2 b2 = __half22float2(Bt[(size_t)__shfl_sync(0xffffffffu, d, ii + 2) * 32 + lane]);
                float2 b3 = __half22float2(Bt[(size_t)__shfl_sync(0xffffffffu, d, ii + 3) * 32 + lane]);
                sx += fmaxf(ax + b0.x, 0.f); sy += fmaxf(ay + b0.y, 0.f);
                sx += fmaxf(ax + b1.x, 0.f); sy += fmaxf(ay + b1.y, 0.f);
                sx += fmaxf(ax + b2.x, 0.f); sy += fmaxf(ay + b2.y, 0.f);
                sx += fmaxf(ax + b3.x, 0.f); sy += fmaxf(ay + b3.y, 0.f);
            }
            for (; ii < mm; ii++) {
                int di = __shfl_sync(0xffffffffu, d, ii);
                float2 bv = __half22float2(Bt[(size_t)di * 32 + lane]);
                sx += fmaxf(ax + bv.x, 0.f);
                sy += fmaxf(ay + bv.y, 0.f);
            }
        }
        float scale = g_w[t] / (float)max(c, 1);
        ox = fmaf(scale, sx, ox);
        oy = fmaf(scale, sy, oy);
    }
    float2 o = make_float2(ox, oy);
    *(float2*)&out[(size_t)n * 64 + 2 * lane] = o;
}

// ---------------- launch: forked graph; code order puts k_finalize 4th? ----
// keep gemm 4th is done; this round leave order (gemm #4) -> next round
// reorder to profile finalize.
extern "C" void kernel_launch(void* const* d_in, const int* in_sizes, int n_in,
                              void* d_out, int out_size) {
    const float* x     = (const float*)d_in[0];  // (N, 64)
    const float* W     = (const float*)d_in[1];  // (T, 128, 64)
    const float* bias  = (const float*)d_in[2];  // (T, 64)
    const float* ea    = (const float*)d_in[3];  // (T,)
    const int*   edges = (const int*)d_in[4];    // (T, 2, E)
    float* out = (float*)d_out;

    (void)in_sizes; (void)n_in; (void)out_size;

    static cudaStream_t s2 = nullptr;
    static cudaEvent_t evFork = nullptr, evJoin = nullptr;
    static int gemm_smem = 4 * 128 * BS * sizeof(__nv_bfloat16);  // 73728 B
    if (!s2) {
        cudaStreamCreateWithFlags(&s2, cudaStreamNonBlocking);
        cudaEventCreateWithFlags(&evFork, cudaEventDisableTiming);
        cudaEventCreateWithFlags(&evJoin, cudaEventDisableTiming);
        cudaFuncSetAttribute(k_gemm, cudaFuncAttributeMaxDynamicSharedMemorySize,
                             gemm_smem);
    }

    // fork point
    cudaEventRecord(evFork, 0);
    cudaStreamWaitEvent(s2, evFork, 0);

    // edge chain start on s2; feature chain on main. k_finalize is launch #4?
    // No: keep heavy kernels profiled round-robin. This round put finalize 4th:
    // #1 zero(s2) #2 softmax #3 split #4... we need gemm BEFORE finalize in
    // DAG but code order is free. Put finalize 4th in code order:
    k_zero_cnt<<<(M_TOT + 255) / 256, 256, 0, s2>>>();        // #1 (edge, s2)
    k_softmax<<<1, 32>>>(ea);                                 // #2 (feat)
    k_split_xw<<<XSPLIT_BLOCKS + WSPLIT_BLOCKS, 256>>>(x, W); // #3 (feat)
    dim3 ggrid((NN + 127) / 128, T_STEPS);
    k_gemm<<<ggrid, 256, gemm_smem>>>();                      // #4 (feat)

    k_hist<<<(T_STEPS * EE + 255) / 256, 256, 0, s2>>>(edges);
    k_scan1<<<NCHUNK, 256, 0, s2>>>();
    k_scan2<<<1, 512, 0, s2>>>();
    k_scan3<<<NCHUNK, 256, 0, s2>>>();
    k_scatter<<<(T_STEPS * EE + 255) / 256, 256, 0, s2>>>(edges);

    // join and finalize
    cudaEventRecord(evJoin, s2);
    cudaStreamWaitEvent(0, evJoin, 0);
    k_finalize<<<(NN * 32 + 255) / 256, 256>>>(bias, out);
}

// round 14
// speedup vs baseline: 1.0324x; 1.0324x over previous
#include <cuda_runtime.h>
#include <cuda_bf16.h>
#include <cuda_fp16.h>
#include <cstdint>

#define T_STEPS 5
#define NN 100000
#define DD 64
#define EE 400000

#define M_TOT (T_STEPS * NN)            // 500000 (t,node) rows
#define CHUNK 1024
#define NCHUNK ((M_TOT + CHUNK - 1) / CHUNK)  // 489

// ---------------- device scratch (static globals: allocation-free) ----------
__device__ float  g_A[(size_t)T_STEPS * NN * DD];   // x @ W_top  (128 MB, fp32)
__device__ __half g_Bh[(size_t)T_STEPS * NN * DD];  // x @ W_bot  (64 MB, fp16)
__device__ __nv_bfloat16 g_xh[(size_t)NN * DD];     // x hi split
__device__ __nv_bfloat16 g_xl[(size_t)NN * DD];     // x lo split
__device__ __nv_bfloat16 g_wh[(size_t)T_STEPS * 128 * 64];  // W hi, [t][j][k]
__device__ __nv_bfloat16 g_wl[(size_t)T_STEPS * 128 * 64];  // W lo, [t][j][k]
__device__ int   g_cnt[M_TOT];
__device__ int   g_rowptr[M_TOT];
__device__ int   g_cursor[M_TOT];
__device__ int   g_sdst[(size_t)T_STEPS * EE];      // dst sorted by (t,src)
__device__ int   g_chunksum[NCHUNK];
__device__ int   g_chunkoff[NCHUNK];
__device__ float g_w[T_STEPS];

// ---------------- helpers ----------------------------------------------------
__device__ __forceinline__ uint32_t pack_bf2(__nv_bfloat16 a, __nv_bfloat16 b) {
    __nv_bfloat162 p = __halves2bfloat162(a, b);
    return *(uint32_t*)&p;
}

__device__ __forceinline__ void mma_bf16(float* c, const uint32_t* a,
                                         uint32_t b0, uint32_t b1) {
    asm("mma.sync.aligned.m16n8k16.row.col.f32.bf16.bf16.f32 "
        "{%0,%1,%2,%3}, {%4,%5,%6,%7}, {%8,%9}, {%0,%1,%2,%3};"
        : "+f"(c[0]), "+f"(c[1]), "+f"(c[2]), "+f"(c[3])
        : "r"(a[0]), "r"(a[1]), "r"(a[2]), "r"(a[3]), "r"(b0), "r"(b1));
}

// ---------------- fused split kernel (x and W halves by block range) --------
#define XSPLIT_BLOCKS 6250   // NN*DD/4 / 256
#define WSPLIT_BLOCKS 160    // T*128*64 / 256
__global__ void k_split_xw(const float* __restrict__ x,
                           const float* __restrict__ W) {
    int b = blockIdx.x;
    if (b < XSPLIT_BLOCKS) {
        int i = b * 256 + threadIdx.x;
        if (i >= NN * DD / 4) return;
        float4 v = ((const float4*)x)[i];
        __nv_bfloat16 h0 = __float2bfloat16(v.x);
        __nv_bfloat16 h1 = __float2bfloat16(v.y);
        __nv_bfloat16 h2 = __float2bfloat16(v.z);
        __nv_bfloat16 h3 = __float2bfloat16(v.w);
        __nv_bfloat16 l0 = __float2bfloat16(v.x - __bfloat162float(h0));
        __nv_bfloat16 l1 = __float2bfloat16(v.y - __bfloat162float(h1));
        __nv_bfloat16 l2 = __float2bfloat16(v.z - __bfloat162float(h2));
        __nv_bfloat16 l3 = __float2bfloat16(v.w - __bfloat162float(h3));
        ((uint2*)g_xh)[i] = make_uint2(pack_bf2(h0, h1), pack_bf2(h2, h3));
        ((uint2*)g_xl)[i] = make_uint2(pack_bf2(l0, l1), pack_bf2(l2, l3));
    } else {
        int i = (b - XSPLIT_BLOCKS) * 256 + threadIdx.x;
        if (i >= T_STEPS * 128 * 64) return;
        int t = i >> 13;
        int j = (i >> 6) & 127;
        int k = i & 63;
        int kcat = k + ((j >> 6) << 6);
        float v = W[(size_t)t * 8192 + kcat * 64 + (j & 63)];
        __nv_bfloat16 h = __float2bfloat16(v);
        __nv_bfloat16 l = __float2bfloat16(v - __bfloat162float(h));
        g_wh[i] = h;
        g_wl[i] = l;
    }
}

// ---------------- tiny kernels ---------------------------------------------
__global__ void k_zero_cnt() {
    int i = blockIdx.x * blockDim.x + threadIdx.x;
    if (i < M_TOT) g_cnt[i] = 0;
}

__global__ void k_softmax(const float* __restrict__ ea) {
    if (threadIdx.x == 0) {
        float m = ea[0];
        for (int t = 1; t < T_STEPS; t++) m = fmaxf(m, ea[t]);
        float s = 0.f, e[T_STEPS];
        for (int t = 0; t < T_STEPS; t++) { e[t] = __expf(ea[t] - m); s += e[t]; }
        for (int t = 0; t < T_STEPS; t++) g_w[t] = e[t] / s;
    }
}

// 2D grid: blockIdx.y = t
__global__ void k_hist(const int* __restrict__ edges) {
    int e = blockIdx.x * blockDim.x + threadIdx.x;
    if (e >= EE) return;
    int t = blockIdx.y;
    int src = edges[(size_t)t * 2 * EE + e];
    atomicAdd(&g_cnt[t * NN + src], 1);
}

__global__ void k_scan1() {
    __shared__ int sh[256];
    int c = blockIdx.x, tid = threadIdx.x;
    int base = c * CHUNK;
    int s = 0;
    #pragma unroll
    for (int i = 0; i < CHUNK / 256; i++) {
        int idx = base + i * 256 + tid;
        if (idx < M_TOT) s += g_cnt[idx];
    }
    sh[tid] = s; __syncthreads();
    for (int off = 128; off > 0; off >>= 1) {
        if (tid < off) sh[tid] += sh[tid + off];
        __syncthreads();
    }
    if (tid == 0) g_chunksum[c] = sh[0];
}

// single-block parallel exclusive scan over NCHUNK chunk sums (512 threads)
__global__ void k_scan2() {
    __shared__ int sh[512];
    int tid = threadIdx.x;
    int v = (tid < NCHUNK) ? g_chunksum[tid] : 0;
    sh[tid] = v; __syncthreads();
    for (int off = 1; off < 512; off <<= 1) {
        int add = (tid >= off) ? sh[tid - off] : 0;
        __syncthreads();
        sh[tid] += add;
        __syncthreads();
    }
    if (tid < NCHUNK) g_chunkoff[tid] = sh[tid] - v;
}

__global__ void k_scan3() {
    __shared__ int sh[256];
    int c = blockIdx.x, tid = threadIdx.x;
    const int PT = CHUNK / 256;  // 4
    int base = c * CHUNK + tid * PT;
    int v[PT];
    int s = 0;
    #pragma unroll
    for (int i = 0; i < PT; i++) {
        int idx = base + i;
        int cv = (idx < M_TOT) ? g_cnt[idx] : 0;
        v[i] = s; s += cv;
    }
    sh[tid] = s; __syncthreads();
    for (int off = 1; off < 256; off <<= 1) {
        int add = (tid >= off) ? sh[tid - off] : 0;
        __syncthreads();
        sh[tid] += add;
        __syncthreads();
    }
    int texcl = ((tid > 0) ? sh[tid - 1] : 0) + g_chunkoff[c];
    #pragma unroll
    for (int i = 0; i < PT; i++) {
        int idx = base + i;
        if (idx < M_TOT) {
            int o = texcl + v[i];
            g_rowptr[idx] = o;
            g_cursor[idx] = o;
        }
    }
}

// 2D grid: blockIdx.y = t
__global__ void k_scatter(const int* __restrict__ edges) {
    int e = blockIdx.x * blockDim.x + threadIdx.x;
    if (e >= EE) return;
    int t = blockIdx.y;
    int src = edges[(size_t)t * 2 * EE + e];
    int dst = edges[(size_t)t * 2 * EE + EE + e];
    int pos = atomicAdd(&g_cursor[t * NN + src], 1);
    g_sdst[pos] = dst;
}

// ---------------- GEMM via split-bf16 tensor cores --------------------------
// A half (j<64) -> g_A fp32 ; B half (j>=64) -> g_Bh fp16.
#define BS 72
__global__ void __launch_bounds__(256) k_gemm() {
    extern __shared__ __nv_bfloat16 smem[];
    __nv_bfloat16* xh_s = smem;                  // [128][BS]
    __nv_bfloat16* xl_s = smem + 128 * BS;
    __nv_bfloat16* wh_s = smem + 2 * 128 * BS;   // [128 j][BS k]
    __nv_bfloat16* wl_s = smem + 3 * 128 * BS;

    int t   = blockIdx.y;
    int n0  = blockIdx.x * 128;
    int tid = threadIdx.x;

    #pragma unroll
    for (int j = 0; j < 4; j++) {
        int idx = tid + j * 256;
        int nl = idx >> 3, kq = idx & 7;
        int n = n0 + nl;
        uint4 hv = make_uint4(0, 0, 0, 0), lv = make_uint4(0, 0, 0, 0);
        if (n < NN) {
            hv = ((const uint4*)g_xh)[((size_t)n * 64 >> 3) + kq];
            lv = ((const uint4*)g_xl)[((size_t)n * 64 >> 3) + kq];
        }
        ((uint4*)xh_s)[nl * 9 + kq] = hv;
        ((uint4*)xl_s)[nl * 9 + kq] = lv;
    }
    const uint4* whg = (const uint4*)(g_wh + (size_t)t * 8192);
    const uint4* wlg = (const uint4*)(g_wl + (size_t)t * 8192);
    #pragma unroll
    for (int j = 0; j < 4; j++) {
        int idx = tid + j * 256;
        int jr = idx >> 3, kq = idx & 7;
        ((uint4*)wh_s)[jr * 9 + kq] = whg[idx];
        ((uint4*)wl_s)[jr * 9 + kq] = wlg[idx];
    }
    __syncthreads();

    int wid = tid >> 5, lane = tid & 31;
    int warp_m = wid & 3, warp_n = wid >> 2;
    int g = lane >> 2, tg = lane & 3;

    float acc[2][8][4];
    #pragma unroll
    for (int mf = 0; mf < 2; mf++)
        #pragma unroll
        for (int nf = 0; nf < 8; nf++)
            #pragma unroll
            for (int r = 0; r < 4; r++) acc[mf][nf][r] = 0.f;

    #pragma unroll
    for (int ks = 0; ks < 4; ks++) {
        int kk = ks * 16;
        uint32_t ah[2][4], al[2][4];
        #pragma unroll
        for (int mf = 0; mf < 2; mf++) {
            int r0 = warp_m * 32 + mf * 16 + g;
            int k0 = kk + 2 * tg;
            ah[mf][0] = *(const uint32_t*)&xh_s[r0 * BS + k0];
            ah[mf][1] = *(const uint32_t*)&xh_s[(r0 + 8) * BS + k0];
            ah[mf][2] = *(const uint32_t*)&xh_s[r0 * BS + k0 + 8];
            ah[mf][3] = *(const uint32_t*)&xh_s[(r0 + 8) * BS + k0 + 8];
            al[mf][0] = *(const uint32_t*)&xl_s[r0 * BS + k0];
            al[mf][1] = *(const uint32_t*)&xl_s[(r0 + 8) * BS + k0];
            al[mf][2] = *(const uint32_t*)&xl_s[r0 * BS + k0 + 8];
            al[mf][3] = *(const uint32_t*)&xl_s[(r0 + 8) * BS + k0 + 8];
        }
        #pragma unroll
        for (int nf = 0; nf < 8; nf++) {
            int col = warp_n * 64 + nf * 8 + g;
            int k0 = kk + 2 * tg;
            uint32_t bh0 = *(const uint32_t*)&wh_s[col * BS + k0];
            uint32_t bh1 = *(const uint32_t*)&wh_s[col * BS + k0 + 8];
            uint32_t bl0 = *(const uint32_t*)&wl_s[col * BS + k0];
            uint32_t bl1 = *(const uint32_t*)&wl_s[col * BS + k0 + 8];
            #pragma unroll
            for (int mf = 0; mf < 2; mf++) {
                mma_bf16(acc[mf][nf], ah[mf], bh0, bh1);
                mma_bf16(acc[mf][nf], ah[mf], bl0, bl1);
                mma_bf16(acc[mf][nf], al[mf], bh0, bh1);
            }
        }
    }

    // epilogue: warp_n==0 -> g_A (fp32), warp_n==1 -> g_Bh (fp16)
    #pragma unroll
    for (int mf = 0; mf < 2; mf++) {
        int rb = warp_m * 32 + mf * 16;
        int nA = n0 + rb + g;
        int nB = n0 + rb + g + 8;
        #pragma unroll
        for (int nf = 0; nf < 8; nf++) {
            int jc = nf * 8 + 2 * tg;
            if (warp_n == 0) {
                if (nA < NN) {
                    float2 v = make_float2(acc[mf][nf][0], acc[mf][nf][1]);
                    *(float2*)&g_A[((size_t)t * NN + nA) * 64 + jc] = v;
                }
                if (nB < NN) {
                    float2 v = make_float2(acc[mf][nf][2], acc[mf][nf][3]);
                    *(float2*)&g_A[((size_t)t * NN + nB) * 64 + jc] = v;
                }
            } else {
                if (nA < NN) {
                    __half2 v = __floats2half2_rn(acc[mf][nf][0], acc[mf][nf][1]);
                    *(__half2*)&g_Bh[((size_t)t * NN + nA) * 64 + jc] = v;
                }
                if (nB < NN) {
                    __half2 v = __floats2half2_rn(acc[mf][nf][2], acc[mf][nf][3]);
                    *(__half2*)&g_Bh[((size_t)t * NN + nB) * 64 + jc] = v;
                }
            }
        }
    }
}

// ---------------- finalize: warp per (t, node), smem reduce over t ----------
// 320 threads = 10 warps = 2 nodes x 5 t. Each warp handles one (t,n) with a
// single latency round of gathers; 128 threads reduce 5 t-partials -> out.
#define FIN_NPB 2
__global__ void __launch_bounds__(320) k_finalize(const float* __restrict__ bias,
                                                  float* __restrict__ out) {
    __shared__ float red[FIN_NPB][T_STEPS][64];
    int tid = threadIdx.x;
    int wid = tid >> 5, lane = tid & 31;
    int slot = wid / T_STEPS;          // 0..1
    int t    = wid - slot * T_STEPS;   // 0..4
    int n = blockIdx.x * FIN_NPB + slot;

    if (n < NN) {
        int row = t * NN + n;
        int beg = g_rowptr[row];
        int c   = g_cnt[row];
        float2 a  = *(const float2*)&g_A[(size_t)row * 64 + 2 * lane];
        float2 bi = *(const float2*)&bias[t * 64 + 2 * lane];
        float ax = a.x + bi.x, ay = a.y + bi.y;
        const __half2* Bt = (const __half2*)(g_Bh + (size_t)t * NN * 64);

        int dv = (lane < c) ? g_sdst[beg + lane] : 0;

        float sx = 0.f, sy = 0.f;
        int m = min(32, c);
        int i = 0;
        for (; i + 8 <= m; i += 8) {
            float2 bv[8];
            #pragma unroll
            for (int q = 0; q < 8; q++) {
                int dq = __shfl_sync(0xffffffffu, dv, i + q);
                bv[q] = __half22float2(Bt[(size_t)dq * 32 + lane]);
            }
            #pragma unroll
            for (int q = 0; q < 8; q++) {
                sx += fmaxf(ax + bv[q].x, 0.f);
                sy += fmaxf(ay + bv[q].y, 0.f);
            }
        }
        if (i + 4 <= m) {
            float2 bv[4];
            #pragma unroll
            for (int q = 0; q < 4; q++) {
                int dq = __shfl_sync(0xffffffffu, dv, i + q);
                bv[q] = __half22float2(Bt[(size_t)dq * 32 + lane]);
            }
            #pragma unroll
            for (int q = 0; q < 4; q++) {
                sx += fmaxf(ax + bv[q].x, 0.f);
                sy += fmaxf(ay + bv[q].y, 0.f);
            }
            i += 4;
        }
        for (; i < m; i++) {
            int di = __shfl_sync(0xffffffffu, dv, i);
            float2 bv = __half22float2(Bt[(size_t)di * 32 + lane]);
            sx += fmaxf(ax + bv.x, 0.f);
            sy += fmaxf(ay + bv.y, 0.f);
        }
        // rare tail: degree > 32
        for (int base = 32; base < c; base += 32) {
            int mm = min(32, c - base);
            int d = (lane < mm) ? g_sdst[beg + base + lane] : 0;
            for (int ii = 0; ii < mm; ii++) {
                int di = __shfl_sync(0xffffffffu, d, ii);
                float2 bv = __half22float2(Bt[(size_t)di * 32 + lane]);
                sx += fmaxf(ax + bv.x, 0.f);
                sy += fmaxf(ay + bv.y, 0.f);
            }
        }
        float scale = g_w[t] / (float)max(c, 1);
        red[slot][t][2 * lane]     = scale * sx;
        red[slot][t][2 * lane + 1] = scale * sy;
    }
    __syncthreads();

    if (tid < FIN_NPB * 64) {
        int s = tid >> 6, d = tid & 63;
        int n2 = blockIdx.x * FIN_NPB + s;
        if (n2 < NN) {
            float v = 0.f;
            #pragma unroll
            for (int tt = 0; tt < T_STEPS; tt++) v += red[s][tt][d];
            out[(size_t)n2 * 64 + d] = v;
        }
    }
}

// ---------------- launch: forked graph; k_hist is launch #4 for ncu ---------
extern "C" void kernel_launch(void* const* d_in, const int* in_sizes, int n_in,
                              void* d_out, int out_size) {
    const float* x     = (const float*)d_in[0];  // (N, 64)
    const float* W     = (const float*)d_in[1];  // (T, 128, 64)
    const float* bias  = (const float*)d_in[2];  // (T, 64)
    const float* ea    = (const float*)d_in[3];  // (T,)
    const int*   edges = (const int*)d_in[4];    // (T, 2, E)
    float* out = (float*)d_out;

    (void)in_sizes; (void)n_in; (void)out_size;

    static cudaStream_t s2 = nullptr;
    static cudaEvent_t evFork = nullptr, evJoin = nullptr;
    static int gemm_smem = 4 * 128 * BS * sizeof(__nv_bfloat16);  // 73728 B
    if (!s2) {
        cudaStreamCreateWithFlags(&s2, cudaStreamNonBlocking);
        cudaEventCreateWithFlags(&evFork, cudaEventDisableTiming);
        cudaEventCreateWithFlags(&evJoin, cudaEventDisableTiming);
        cudaFuncSetAttribute(k_gemm, cudaFuncAttributeMaxDynamicSharedMemorySize,
                             gemm_smem);
    }

    // fork point
    cudaEventRecord(evFork, 0);
    cudaStreamWaitEvent(s2, evFork, 0);

    dim3 egrid((EE + 255) / 256, T_STEPS);

    k_zero_cnt<<<(M_TOT + 255) / 256, 256, 0, s2>>>();        // #1 (edge, s2)
    k_softmax<<<1, 32>>>(ea);                                 // #2 (feat)
    k_split_xw<<<XSPLIT_BLOCKS + WSPLIT_BLOCKS, 256>>>(x, W); // #3 (feat)
    k_hist<<<egrid, 256, 0, s2>>>(edges);                     // #4 (edge) <- ncu
    dim3 ggrid((NN + 127) / 128, T_STEPS);
    k_gemm<<<ggrid, 256, gemm_smem>>>();                      // #5 (feat)

    k_scan1<<<NCHUNK, 256, 0, s2>>>();
    k_scan2<<<1, 512, 0, s2>>>();
    k_scan3<<<NCHUNK, 256, 0, s2>>>();
    k_scatter<<<egrid, 256, 0, s2>>>(edges);

    // join and finalize
    cudaEventRecord(evJoin, s2);
    cudaStreamWaitEvent(0, evJoin, 0);
    k_finalize<<<(NN + FIN_NPB - 1) / FIN_NPB, 320>>>(bias, out);
}

// round 15
// speedup vs baseline: 1.0707x; 1.0370x over previous
#include <cuda_runtime.h>
#include <cuda_bf16.h>
#include <cuda_fp16.h>
#include <cstdint>

#define T_STEPS 5
#define NN 100000
#define DD 64
#define EE 400000

#define M_TOT (T_STEPS * NN)            // 500000 (t,node) rows
#define CHUNK 1024
#define NCHUNK ((M_TOT + CHUNK - 1) / CHUNK)  // 489

// ---------------- device scratch (static globals: allocation-free) ----------
__device__ __half g_Ah[(size_t)T_STEPS * NN * DD];  // x @ W_top  (64 MB, fp16)
__device__ __half g_Bh[(size_t)T_STEPS * NN * DD];  // x @ W_bot  (64 MB, fp16)
__device__ __nv_bfloat16 g_xh[(size_t)NN * DD];     // x hi split
__device__ __nv_bfloat16 g_xl[(size_t)NN * DD];     // x lo split
__device__ __nv_bfloat16 g_wh[(size_t)T_STEPS * 128 * 64];  // W hi, [t][j][k]
__device__ __nv_bfloat16 g_wl[(size_t)T_STEPS * 128 * 64];  // W lo, [t][j][k]
__device__ int   g_cnt[M_TOT];
__device__ int   g_rowptr[M_TOT];
__device__ int   g_cursor[M_TOT];
__device__ int   g_sdst[(size_t)T_STEPS * EE];      // dst sorted by (t,src)
__device__ int   g_chunksum[NCHUNK];
__device__ int   g_chunkoff[NCHUNK];
__device__ float g_w[T_STEPS];

// ---------------- helpers ----------------------------------------------------
__device__ __forceinline__ uint32_t pack_bf2(__nv_bfloat16 a, __nv_bfloat16 b) {
    __nv_bfloat162 p = __halves2bfloat162(a, b);
    return *(uint32_t*)&p;
}

__device__ __forceinline__ void mma_bf16(float* c, const uint32_t* a,
                                         uint32_t b0, uint32_t b1) {
    asm("mma.sync.aligned.m16n8k16.row.col.f32.bf16.bf16.f32 "
        "{%0,%1,%2,%3}, {%4,%5,%6,%7}, {%8,%9}, {%0,%1,%2,%3};"
        : "+f"(c[0]), "+f"(c[1]), "+f"(c[2]), "+f"(c[3])
        : "r"(a[0]), "r"(a[1]), "r"(a[2]), "r"(a[3]), "r"(b0), "r"(b1));
}

__device__ __forceinline__ void ldsm4(uint32_t addr, uint32_t* r) {
    asm volatile("ldmatrix.sync.aligned.m8n8.x4.shared.b16 {%0,%1,%2,%3}, [%4];"
        : "=r"(r[0]), "=r"(r[1]), "=r"(r[2]), "=r"(r[3]) : "r"(addr));
}

// ---------------- fused split kernel (x and W halves by block range) --------
#define XSPLIT_BLOCKS 6250   // NN*DD/4 / 256
#define WSPLIT_BLOCKS 160    // T*128*64 / 256
__global__ void k_split_xw(const float* __restrict__ x,
                           const float* __restrict__ W) {
    int b = blockIdx.x;
    if (b < XSPLIT_BLOCKS) {
        int i = b * 256 + threadIdx.x;
        if (i >= NN * DD / 4) return;
        float4 v = ((const float4*)x)[i];
        __nv_bfloat16 h0 = __float2bfloat16(v.x);
        __nv_bfloat16 h1 = __float2bfloat16(v.y);
        __nv_bfloat16 h2 = __float2bfloat16(v.z);
        __nv_bfloat16 h3 = __float2bfloat16(v.w);
        __nv_bfloat16 l0 = __float2bfloat16(v.x - __bfloat162float(h0));
        __nv_bfloat16 l1 = __float2bfloat16(v.y - __bfloat162float(h1));
        __nv_bfloat16 l2 = __float2bfloat16(v.z - __bfloat162float(h2));
        __nv_bfloat16 l3 = __float2bfloat16(v.w - __bfloat162float(h3));
        ((uint2*)g_xh)[i] = make_uint2(pack_bf2(h0, h1), pack_bf2(h2, h3));
        ((uint2*)g_xl)[i] = make_uint2(pack_bf2(l0, l1), pack_bf2(l2, l3));
    } else {
        int i = (b - XSPLIT_BLOCKS) * 256 + threadIdx.x;
        if (i >= T_STEPS * 128 * 64) return;
        int t = i >> 13;
        int j = (i >> 6) & 127;
        int k = i & 63;
        int kcat = k + ((j >> 6) << 6);
        float v = W[(size_t)t * 8192 + kcat * 64 + (j & 63)];
        __nv_bfloat16 h = __float2bfloat16(v);
        __nv_bfloat16 l = __float2bfloat16(v - __bfloat162float(h));
        g_wh[i] = h;
        g_wl[i] = l;
    }
}

// ---------------- tiny kernels ---------------------------------------------
__global__ void k_zero_cnt() {
    int i = blockIdx.x * blockDim.x + threadIdx.x;
    if (i < M_TOT) g_cnt[i] = 0;
}

__global__ void k_softmax(const float* __restrict__ ea) {
    if (threadIdx.x == 0) {
        float m = ea[0];
        for (int t = 1; t < T_STEPS; t++) m = fmaxf(m, ea[t]);
        float s = 0.f, e[T_STEPS];
        for (int t = 0; t < T_STEPS; t++) { e[t] = __expf(ea[t] - m); s += e[t]; }
        for (int t = 0; t < T_STEPS; t++) g_w[t] = e[t] / s;
    }
}

// 2D grid: blockIdx.y = t
__global__ void k_hist(const int* __restrict__ edges) {
    int e = blockIdx.x * blockDim.x + threadIdx.x;
    if (e >= EE) return;
    int t = blockIdx.y;
    int src = edges[(size_t)t * 2 * EE + e];
    atomicAdd(&g_cnt[t * NN + src], 1);
}

__global__ void k_scan1() {
    __shared__ int sh[256];
    int c = blockIdx.x, tid = threadIdx.x;
    int base = c * CHUNK;
    int s = 0;
    #pragma unroll
    for (int i = 0; i < CHUNK / 256; i++) {
        int idx = base + i * 256 + tid;
        if (idx < M_TOT) s += g_cnt[idx];
    }
    sh[tid] = s; __syncthreads();
    for (int off = 128; off > 0; off >>= 1) {
        if (tid < off) sh[tid] += sh[tid + off];
        __syncthreads();
    }
    if (tid == 0) g_chunksum[c] = sh[0];
}

// single-block parallel exclusive scan over NCHUNK chunk sums (512 threads)
__global__ void k_scan2() {
    __shared__ int sh[512];
    int tid = threadIdx.x;
    int v = (tid < NCHUNK) ? g_chunksum[tid] : 0;
    sh[tid] = v; __syncthreads();
    for (int off = 1; off < 512; off <<= 1) {
        int add = (tid >= off) ? sh[tid - off] : 0;
        __syncthreads();
        sh[tid] += add;
        __syncthreads();
    }
    if (tid < NCHUNK) g_chunkoff[tid] = sh[tid] - v;
}

__global__ void k_scan3() {
    __shared__ int sh[256];
    int c = blockIdx.x, tid = threadIdx.x;
    const int PT = CHUNK / 256;  // 4
    int base = c * CHUNK + tid * PT;
    int v[PT];
    int s = 0;
    #pragma unroll
    for (int i = 0; i < PT; i++) {
        int idx = base + i;
        int cv = (idx < M_TOT) ? g_cnt[idx] : 0;
        v[i] = s; s += cv;
    }
    sh[tid] = s; __syncthreads();
    for (int off = 1; off < 256; off <<= 1) {
        int add = (tid >= off) ? sh[tid - off] : 0;
        __syncthreads();
        sh[tid] += add;
        __syncthreads();
    }
    int texcl = ((tid > 0) ? sh[tid - 1] : 0) + g_chunkoff[c];
    #pragma unroll
    for (int i = 0; i < PT; i++) {
        int idx = base + i;
        if (idx < M_TOT) {
            int o = texcl + v[i];
            g_rowptr[idx] = o;
            g_cursor[idx] = o;
        }
    }
}

// 2D grid: blockIdx.y = t
__global__ void k_scatter(const int* __restrict__ edges) {
    int e = blockIdx.x * blockDim.x + threadIdx.x;
    if (e >= EE) return;
    int t = blockIdx.y;
    int src = edges[(size_t)t * 2 * EE + e];
    int dst = edges[(size_t)t * 2 * EE + EE + e];
    int pos = atomicAdd(&g_cursor[t * NN + src], 1);
    g_sdst[pos] = dst;
}

// ---------------- GEMM via split-bf16 tensor cores + ldmatrix ---------------
// A half (j<64) -> g_Ah fp16 ; B half (j>=64) -> g_Bh fp16.
#define BS 72
__global__ void __launch_bounds__(256) k_gemm() {
    extern __shared__ __nv_bfloat16 smem[];
    __nv_bfloat16* xh_s = smem;                  // [128][BS]
    __nv_bfloat16* xl_s = smem + 128 * BS;
    __nv_bfloat16* wh_s = smem + 2 * 128 * BS;   // [128 j][BS k]
    __nv_bfloat16* wl_s = smem + 3 * 128 * BS;

    int t   = blockIdx.y;
    int n0  = blockIdx.x * 128;
    int tid = threadIdx.x;

    #pragma unroll
    for (int j = 0; j < 4; j++) {
        int idx = tid + j * 256;
        int nl = idx >> 3, kq = idx & 7;
        int n = n0 + nl;
        uint4 hv = make_uint4(0, 0, 0, 0), lv = make_uint4(0, 0, 0, 0);
        if (n < NN) {
            hv = ((const uint4*)g_xh)[((size_t)n * 64 >> 3) + kq];
            lv = ((const uint4*)g_xl)[((size_t)n * 64 >> 3) + kq];
        }
        ((uint4*)xh_s)[nl * 9 + kq] = hv;
        ((uint4*)xl_s)[nl * 9 + kq] = lv;
    }
    const uint4* whg = (const uint4*)(g_wh + (size_t)t * 8192);
    const uint4* wlg = (const uint4*)(g_wl + (size_t)t * 8192);
    #pragma unroll
    for (int j = 0; j < 4; j++) {
        int idx = tid + j * 256;
        int jr = idx >> 3, kq = idx & 7;
        ((uint4*)wh_s)[jr * 9 + kq] = whg[idx];
        ((uint4*)wl_s)[jr * 9 + kq] = wlg[idx];
    }
    __syncthreads();

    int wid = tid >> 5, lane = tid & 31;
    int warp_m = wid & 3, warp_n = wid >> 2;
    int g = lane >> 2, tg = lane & 3;

    // ldmatrix lane addressing: matrices M0..M3 <- lanes 0-7/8-15/16-23/24-31
    int rowSel = (lane & 7) + ((lane & 8) ? 8 : 0);
    int colSel = (lane & 16) ? 8 : 0;
    uint32_t sbase = (uint32_t)__cvta_generic_to_shared(smem);
    const uint32_t OXH = 0;
    const uint32_t OXL = 128 * BS * 2;
    const uint32_t OWH = 2 * 128 * BS * 2;
    const uint32_t OWL = 3 * 128 * BS * 2;

    uint32_t aBaseH[2], aBaseL[2];
    #pragma unroll
    for (int mf = 0; mf < 2; mf++) {
        uint32_t off = ((warp_m * 32 + mf * 16 + rowSel) * BS + colSel) * 2;
        aBaseH[mf] = sbase + OXH + off;
        aBaseL[mf] = sbase + OXL + off;
    }
    uint32_t bBaseH[4], bBaseL[4];
    #pragma unroll
    for (int p = 0; p < 4; p++) {
        uint32_t off = ((warp_n * 64 + p * 16 + rowSel) * BS + colSel) * 2;
        bBaseH[p] = sbase + OWH + off;
        bBaseL[p] = sbase + OWL + off;
    }

    float acc[2][8][4];
    #pragma unroll
    for (int mf = 0; mf < 2; mf++)
        #pragma unroll
        for (int nf = 0; nf < 8; nf++)
            #pragma unroll
            for (int r = 0; r < 4; r++) acc[mf][nf][r] = 0.f;

    #pragma unroll
    for (int ks = 0; ks < 4; ks++) {
        uint32_t kkB = ks * 32;   // 16 bf16 = 32 bytes
        uint32_t ah0[4], ah1[4], al0[4], al1[4];
        ldsm4(aBaseH[0] + kkB, ah0);
        ldsm4(aBaseH[1] + kkB, ah1);
        ldsm4(aBaseL[0] + kkB, al0);
        ldsm4(aBaseL[1] + kkB, al1);
        #pragma unroll
        for (int p = 0; p < 4; p++) {
            uint32_t bh[4], bl[4];
            ldsm4(bBaseH[p] + kkB, bh);
            ldsm4(bBaseL[p] + kkB, bl);
            int nf0 = 2 * p, nf1 = 2 * p + 1;
            // nf0: b-regs (bh[0], bh[2]) hi, (bl[0], bl[2]) lo
            mma_bf16(acc[0][nf0], ah0, bh[0], bh[2]);
            mma_bf16(acc[0][nf0], ah0, bl[0], bl[2]);
            mma_bf16(acc[0][nf0], al0, bh[0], bh[2]);
            mma_bf16(acc[1][nf0], ah1, bh[0], bh[2]);
            mma_bf16(acc[1][nf0], ah1, bl[0], bl[2]);
            mma_bf16(acc[1][nf0], al1, bh[0], bh[2]);
            // nf1: b-regs (bh[1], bh[3]) hi, (bl[1], bl[3]) lo
            mma_bf16(acc[0][nf1], ah0, bh[1], bh[3]);
            mma_bf16(acc[0][nf1], ah0, bl[1], bl[3]);
            mma_bf16(acc[0][nf1], al0, bh[1], bh[3]);
            mma_bf16(acc[1][nf1], ah1, bh[1], bh[3]);
            mma_bf16(acc[1][nf1], ah1, bl[1], bl[3]);
            mma_bf16(acc[1][nf1], al1, bh[1], bh[3]);
        }
    }

    // epilogue: warp_n==0 -> g_Ah, warp_n==1 -> g_Bh (both fp16)
    __half* dst = warp_n ? g_Bh : g_Ah;
    #pragma unroll
    for (int mf = 0; mf < 2; mf++) {
        int rb = warp_m * 32 + mf * 16;
        int nA = n0 + rb + g;
        int nB = n0 + rb + g + 8;
        #pragma unroll
        for (int nf = 0; nf < 8; nf++) {
            int jc = nf * 8 + 2 * tg;
            if (nA < NN) {
                __half2 v = __floats2half2_rn(acc[mf][nf][0], acc[mf][nf][1]);
                *(__half2*)&dst[((size_t)t * NN + nA) * 64 + jc] = v;
            }
            if (nB < NN) {
                __half2 v = __floats2half2_rn(acc[mf][nf][2], acc[mf][nf][3]);
                *(__half2*)&dst[((size_t)t * NN + nB) * 64 + jc] = v;
            }
        }
    }
}

// ---------------- finalize: warp per (t, node), smem reduce over t ----------
#define FIN_NPB 2
__global__ void __launch_bounds__(320) k_finalize(const float* __restrict__ bias,
                                                  float* __restrict__ out) {
    __shared__ float red[FIN_NPB][T_STEPS][64];
    int tid = threadIdx.x;
    int wid = tid >> 5, lane = tid & 31;
    int slot = wid / T_STEPS;          // 0..1
    int t    = wid - slot * T_STEPS;   // 0..4
    int n = blockIdx.x * FIN_NPB + slot;

    if (n < NN) {
        int row = t * NN + n;
        int beg = g_rowptr[row];
        int c   = g_cnt[row];
        float2 a  = __half22float2(((const __half2*)(g_Ah + (size_t)row * 64))[lane]);
        float2 bi = *(const float2*)&bias[t * 64 + 2 * lane];
        float ax = a.x + bi.x, ay = a.y + bi.y;
        const __half2* Bt = (const __half2*)(g_Bh + (size_t)t * NN * 64);

        int dv = (lane < c) ? g_sdst[beg + lane] : 0;

        float sx = 0.f, sy = 0.f;
        int m = min(32, c);
        int i = 0;
        for (; i + 8 <= m; i += 8) {
            float2 bv[8];
            #pragma unroll
            for (int q = 0; q < 8; q++) {
                int dq = __shfl_sync(0xffffffffu, dv, i + q);
                bv[q] = __half22float2(Bt[(size_t)dq * 32 + lane]);
            }
            #pragma unroll
            for (int q = 0; q < 8; q++) {
                sx += fmaxf(ax + bv[q].x, 0.f);
                sy += fmaxf(ay + bv[q].y, 0.f);
            }
        }
        if (i + 4 <= m) {
            float2 bv[4];
            #pragma unroll
            for (int q = 0; q < 4; q++) {
                int dq = __shfl_sync(0xffffffffu, dv, i + q);
                bv[q] = __half22float2(Bt[(size_t)dq * 32 + lane]);
            }
            #pragma unroll
            for (int q = 0; q < 4; q++) {
                sx += fmaxf(ax + bv[q].x, 0.f);
                sy += fmaxf(ay + bv[q].y, 0.f);
            }
            i += 4;
        }
        for (; i < m; i++) {
            int di = __shfl_sync(0xffffffffu, dv, i);
            float2 bv = __half22float2(Bt[(size_t)di * 32 + lane]);
            sx += fmaxf(ax + bv.x, 0.f);
            sy += fmaxf(ay + bv.y, 0.f);
        }
        // rare tail: degree > 32
        for (int base = 32; base < c; base += 32) {
            int mm = min(32, c - base);
            int d = (lane < mm) ? g_sdst[beg + base + lane] : 0;
            for (int ii = 0; ii < mm; ii++) {
                int di = __shfl_sync(0xffffffffu, d, ii);
                float2 bv = __half22float2(Bt[(size_t)di * 32 + lane]);
                sx += fmaxf(ax + bv.x, 0.f);
                sy += fmaxf(ay + bv.y, 0.f);
            }
        }
        float scale = g_w[t] / (float)max(c, 1);
        red[slot][t][2 * lane]     = scale * sx;
        red[slot][t][2 * lane + 1] = scale * sy;
    }
    __syncthreads();

    if (tid < FIN_NPB * 64) {
        int s = tid >> 6, d = tid & 63;
        int n2 = blockIdx.x * FIN_NPB + s;
        if (n2 < NN) {
            float v = 0.f;
            #pragma unroll
            for (int tt = 0; tt < T_STEPS; tt++) v += red[s][tt][d];
            out[(size_t)n2 * 64 + d] = v;
        }
    }
}

// ---------------- launch: forked graph; k_gemm is launch #4 for ncu ---------
extern "C" void kernel_launch(void* const* d_in, const int* in_sizes, int n_in,
                              void* d_out, int out_size) {
    const float* x     = (const float*)d_in[0];  // (N, 64)
    const float* W     = (const float*)d_in[1];  // (T, 128, 64)
    const float* bias  = (const float*)d_in[2];  // (T, 64)
    const float* ea    = (const float*)d_in[3];  // (T,)
    const int*   edges = (const int*)d_in[4];    // (T, 2, E)
    float* out = (float*)d_out;

    (void)in_sizes; (void)n_in; (void)out_size;

    static cudaStream_t s2 = nullptr;
    static cudaEvent_t evFork = nullptr, evJoin = nullptr;
    static int gemm_smem = 4 * 128 * BS * sizeof(__nv_bfloat16);  // 73728 B
    if (!s2) {
        cudaStreamCreateWithFlags(&s2, cudaStreamNonBlocking);
        cudaEventCreateWithFlags(&evFork, cudaEventDisableTiming);
        cudaEventCreateWithFlags(&evJoin, cudaEventDisableTiming);
        cudaFuncSetAttribute(k_gemm, cudaFuncAttributeMaxDynamicSharedMemorySize,
                             gemm_smem);
    }

    // fork point
    cudaEventRecord(evFork, 0);
    cudaStreamWaitEvent(s2, evFork, 0);

    dim3 egrid((EE + 255) / 256, T_STEPS);
    dim3 ggrid((NN + 127) / 128, T_STEPS);

    k_zero_cnt<<<(M_TOT + 255) / 256, 256, 0, s2>>>();        // #1 (edge, s2)
    k_softmax<<<1, 32>>>(ea);                                 // #2 (feat)
    k_split_xw<<<XSPLIT_BLOCKS + WSPLIT_BLOCKS, 256>>>(x, W); // #3 (feat)
    k_gemm<<<ggrid, 256, gemm_smem>>>();                      // #4 (feat) <- ncu

    k_hist<<<egrid, 256, 0, s2>>>(edges);
    k_scan1<<<NCHUNK, 256, 0, s2>>>();
    k_scan2<<<1, 512, 0, s2>>>();
    k_scan3<<<NCHUNK, 256, 0, s2>>>();
    k_scatter<<<egrid, 256, 0, s2>>>(edges);

    // join and finalize
    cudaEventRecord(evJoin, s2);
    cudaStreamWaitEvent(0, evJoin, 0);
    k_finalize<<<(NN + FIN_NPB - 1) / FIN_NPB, 320>>>(bias, out);
}

// round 16
// speedup vs baseline: 1.0972x; 1.0248x over previous
#include <cuda_runtime.h>
#include <cuda_bf16.h>
#include <cuda_fp16.h>
#include <cstdint>

#define T_STEPS 5
#define NN 100000
#define DD 64
#define EE 400000

#define M_TOT (T_STEPS * NN)            // 500000 (t,node) rows
#define CHUNK 1024
#define NCHUNK ((M_TOT + CHUNK - 1) / CHUNK)  // 489

// ---------------- device scratch (static globals: allocation-free) ----------
__device__ __half g_Ah[(size_t)T_STEPS * NN * DD];  // x @ W_top  (64 MB, fp16)
__device__ __half g_Bh[(size_t)T_STEPS * NN * DD];  // x @ W_bot  (64 MB, fp16)
__device__ __half g_x16h[(size_t)NN * DD];          // x hi fp16 split
__device__ __half g_x16l[(size_t)NN * DD];          // x lo fp16 split
__device__ __half g_wf16[(size_t)T_STEPS * 128 * 64];  // W fp16, [t][j][k]
__device__ int   g_cnt[M_TOT];
__device__ int   g_rowptr[M_TOT];
__device__ int   g_cursor[M_TOT];
__device__ int   g_sdst[(size_t)T_STEPS * EE];      // dst sorted by (t,src)
__device__ int   g_chunksum[NCHUNK];
__device__ int   g_chunkoff[NCHUNK];
__device__ float g_w[T_STEPS];

// ---------------- helpers ----------------------------------------------------
__device__ __forceinline__ uint32_t pack_h2(__half a, __half b) {
    __half2 p = __halves2half2(a, b);
    return *(uint32_t*)&p;
}

__device__ __forceinline__ void mma_fp16(float* c, const uint32_t* a,
                                         uint32_t b0, uint32_t b1) {
    asm("mma.sync.aligned.m16n8k16.row.col.f32.f16.f16.f32 "
        "{%0,%1,%2,%3}, {%4,%5,%6,%7}, {%8,%9}, {%0,%1,%2,%3};"
        : "+f"(c[0]), "+f"(c[1]), "+f"(c[2]), "+f"(c[3])
        : "r"(a[0]), "r"(a[1]), "r"(a[2]), "r"(a[3]), "r"(b0), "r"(b1));
}

__device__ __forceinline__ void ldsm4(uint32_t addr, uint32_t* r) {
    asm volatile("ldmatrix.sync.aligned.m8n8.x4.shared.b16 {%0,%1,%2,%3}, [%4];"
        : "=r"(r[0]), "=r"(r[1]), "=r"(r[2]), "=r"(r[3]) : "r"(addr));
}

// ---------------- fused split kernel (x and W halves by block range) --------
#define XSPLIT_BLOCKS 6250   // NN*DD/4 / 256
#define WSPLIT_BLOCKS 160    // T*128*64 / 256
__global__ void k_split_xw(const float* __restrict__ x,
                           const float* __restrict__ W) {
    int b = blockIdx.x;
    if (b < XSPLIT_BLOCKS) {
        int i = b * 256 + threadIdx.x;
        if (i >= NN * DD / 4) return;
        float4 v = ((const float4*)x)[i];
        __half h0 = __float2half(v.x);
        __half h1 = __float2half(v.y);
        __half h2 = __float2half(v.z);
        __half h3 = __float2half(v.w);
        __half l0 = __float2half(v.x - __half2float(h0));
        __half l1 = __float2half(v.y - __half2float(h1));
        __half l2 = __float2half(v.z - __half2float(h2));
        __half l3 = __float2half(v.w - __half2float(h3));
        ((uint2*)g_x16h)[i] = make_uint2(pack_h2(h0, h1), pack_h2(h2, h3));
        ((uint2*)g_x16l)[i] = make_uint2(pack_h2(l0, l1), pack_h2(l2, l3));
    } else {
        int i = (b - XSPLIT_BLOCKS) * 256 + threadIdx.x;
        if (i >= T_STEPS * 128 * 64) return;
        int t = i >> 13;
        int j = (i >> 6) & 127;
        int k = i & 63;
        int kcat = k + ((j >> 6) << 6);
        g_wf16[i] = __float2half(W[(size_t)t * 8192 + kcat * 64 + (j & 63)]);
    }
}

// ---------------- tiny kernels ---------------------------------------------
__global__ void k_zero_cnt() {
    int i = blockIdx.x * blockDim.x + threadIdx.x;
    if (i < M_TOT) g_cnt[i] = 0;
}

__global__ void k_softmax(const float* __restrict__ ea) {
    if (threadIdx.x == 0) {
        float m = ea[0];
        for (int t = 1; t < T_STEPS; t++) m = fmaxf(m, ea[t]);
        float s = 0.f, e[T_STEPS];
        for (int t = 0; t < T_STEPS; t++) { e[t] = __expf(ea[t] - m); s += e[t]; }
        for (int t = 0; t < T_STEPS; t++) g_w[t] = e[t] / s;
    }
}

// 2D grid: blockIdx.y = t
__global__ void k_hist(const int* __restrict__ edges) {
    int e = blockIdx.x * blockDim.x + threadIdx.x;
    if (e >= EE) return;
    int t = blockIdx.y;
    int src = edges[(size_t)t * 2 * EE + e];
    atomicAdd(&g_cnt[t * NN + src], 1);
}

__global__ void k_scan1() {
    __shared__ int sh[256];
    int c = blockIdx.x, tid = threadIdx.x;
    int base = c * CHUNK;
    int s = 0;
    #pragma unroll
    for (int i = 0; i < CHUNK / 256; i++) {
        int idx = base + i * 256 + tid;
        if (idx < M_TOT) s += g_cnt[idx];
    }
    sh[tid] = s; __syncthreads();
    for (int off = 128; off > 0; off >>= 1) {
        if (tid < off) sh[tid] += sh[tid + off];
        __syncthreads();
    }
    if (tid == 0) g_chunksum[c] = sh[0];
}

// single-block parallel exclusive scan over NCHUNK chunk sums (512 threads)
__global__ void k_scan2() {
    __shared__ int sh[512];
    int tid = threadIdx.x;
    int v = (tid < NCHUNK) ? g_chunksum[tid] : 0;
    sh[tid] = v; __syncthreads();
    for (int off = 1; off < 512; off <<= 1) {
        int add = (tid >= off) ? sh[tid - off] : 0;
        __syncthreads();
        sh[tid] += add;
        __syncthreads();
    }
    if (tid < NCHUNK) g_chunkoff[tid] = sh[tid] - v;
}

__global__ void k_scan3() {
    __shared__ int sh[256];
    int c = blockIdx.x, tid = threadIdx.x;
    const int PT = CHUNK / 256;  // 4
    int base = c * CHUNK + tid * PT;
    int v[PT];
    int s = 0;
    #pragma unroll
    for (int i = 0; i < PT; i++) {
        int idx = base + i;
        int cv = (idx < M_TOT) ? g_cnt[idx] : 0;
        v[i] = s; s += cv;
    }
    sh[tid] = s; __syncthreads();
    for (int off = 1; off < 256; off <<= 1) {
        int add = (tid >= off) ? sh[tid - off] : 0;
        __syncthreads();
        sh[tid] += add;
        __syncthreads();
    }
    int texcl = ((tid > 0) ? sh[tid - 1] : 0) + g_chunkoff[c];
    #pragma unroll
    for (int i = 0; i < PT; i++) {
        int idx = base + i;
        if (idx < M_TOT) {
            int o = texcl + v[i];
            g_rowptr[idx] = o;
            g_cursor[idx] = o;
        }
    }
}

// 2D grid: blockIdx.y = t
__global__ void k_scatter(const int* __restrict__ edges) {
    int e = blockIdx.x * blockDim.x + threadIdx.x;
    if (e >= EE) return;
    int t = blockIdx.y;
    int src = edges[(size_t)t * 2 * EE + e];
    int dst = edges[(size_t)t * 2 * EE + EE + e];
    int pos = atomicAdd(&g_cursor[t * NN + src], 1);
    g_sdst[pos] = dst;
}

// ---------------- GEMM: 2-product fp16-split tensor cores -------------------
// x = xh + xl (fp16 pair, ~22-bit), W = w16 (fp16).
// C = xh*w16 + xl*w16 : 2 MMA products, 8 LDSM per warp-ks (was 3 / 12).
// A half (j<64) -> g_Ah fp16 ; B half (j>=64) -> g_Bh fp16.
#define BS 72
__global__ void __launch_bounds__(256) k_gemm() {
    extern __shared__ __half smem[];
    __half* xh_s = smem;                  // [128][BS]
    __half* xl_s = smem + 128 * BS;
    __half* w_s  = smem + 2 * 128 * BS;   // [128 j][BS k]

    int t   = blockIdx.y;
    int n0  = blockIdx.x * 128;
    int tid = threadIdx.x;

    #pragma unroll
    for (int j = 0; j < 4; j++) {
        int idx = tid + j * 256;
        int nl = idx >> 3, kq = idx & 7;
        int n = n0 + nl;
        uint4 hv = make_uint4(0, 0, 0, 0), lv = make_uint4(0, 0, 0, 0);
        if (n < NN) {
            hv = ((const uint4*)g_x16h)[((size_t)n * 64 >> 3) + kq];
            lv = ((const uint4*)g_x16l)[((size_t)n * 64 >> 3) + kq];
        }
        ((uint4*)xh_s)[nl * 9 + kq] = hv;
        ((uint4*)xl_s)[nl * 9 + kq] = lv;
    }
    const uint4* wg = (const uint4*)(g_wf16 + (size_t)t * 8192);
    #pragma unroll
    for (int j = 0; j < 4; j++) {
        int idx = tid + j * 256;
        int jr = idx >> 3, kq = idx & 7;
        ((uint4*)w_s)[jr * 9 + kq] = wg[idx];
    }
    __syncthreads();

    int wid = tid >> 5, lane = tid & 31;
    int warp_m = wid & 3, warp_n = wid >> 2;
    int g = lane >> 2, tg = lane & 3;

    // ldmatrix lane addressing
    int rowSel = (lane & 7) + ((lane & 8) ? 8 : 0);
    int colSel = (lane & 16) ? 8 : 0;
    uint32_t sbase = (uint32_t)__cvta_generic_to_shared(smem);
    const uint32_t OXH = 0;
    const uint32_t OXL = 128 * BS * 2;
    const uint32_t OW  = 2 * 128 * BS * 2;

    uint32_t aBaseH[2], aBaseL[2];
    #pragma unroll
    for (int mf = 0; mf < 2; mf++) {
        uint32_t off = ((warp_m * 32 + mf * 16 + rowSel) * BS + colSel) * 2;
        aBaseH[mf] = sbase + OXH + off;
        aBaseL[mf] = sbase + OXL + off;
    }
    uint32_t bBase[4];
    #pragma unroll
    for (int p = 0; p < 4; p++) {
        uint32_t off = ((warp_n * 64 + p * 16 + rowSel) * BS + colSel) * 2;
        bBase[p] = sbase + OW + off;
    }

    float acc[2][8][4];
    #pragma unroll
    for (int mf = 0; mf < 2; mf++)
        #pragma unroll
        for (int nf = 0; nf < 8; nf++)
            #pragma unroll
            for (int r = 0; r < 4; r++) acc[mf][nf][r] = 0.f;

    #pragma unroll
    for (int ks = 0; ks < 4; ks++) {
        uint32_t kkB = ks * 32;   // 16 halves = 32 bytes
        uint32_t ah0[4], ah1[4], al0[4], al1[4];
        ldsm4(aBaseH[0] + kkB, ah0);
        ldsm4(aBaseH[1] + kkB, ah1);
        ldsm4(aBaseL[0] + kkB, al0);
        ldsm4(aBaseL[1] + kkB, al1);
        #pragma unroll
        for (int p = 0; p < 4; p++) {
            uint32_t bb[4];
            ldsm4(bBase[p] + kkB, bb);
            int nf0 = 2 * p, nf1 = 2 * p + 1;
            mma_fp16(acc[0][nf0], ah0, bb[0], bb[2]);
            mma_fp16(acc[0][nf0], al0, bb[0], bb[2]);
            mma_fp16(acc[1][nf0], ah1, bb[0], bb[2]);
            mma_fp16(acc[1][nf0], al1, bb[0], bb[2]);
            mma_fp16(acc[0][nf1], ah0, bb[1], bb[3]);
            mma_fp16(acc[0][nf1], al0, bb[1], bb[3]);
            mma_fp16(acc[1][nf1], ah1, bb[1], bb[3]);
            mma_fp16(acc[1][nf1], al1, bb[1], bb[3]);
        }
    }

    // epilogue: warp_n==0 -> g_Ah, warp_n==1 -> g_Bh (both fp16)
    __half* dst = warp_n ? g_Bh : g_Ah;
    #pragma unroll
    for (int mf = 0; mf < 2; mf++) {
        int rb = warp_m * 32 + mf * 16;
        int nA = n0 + rb + g;
        int nB = n0 + rb + g + 8;
        #pragma unroll
        for (int nf = 0; nf < 8; nf++) {
            int jc = nf * 8 + 2 * tg;
            if (nA < NN) {
                __half2 v = __floats2half2_rn(acc[mf][nf][0], acc[mf][nf][1]);
                *(__half2*)&dst[((size_t)t * NN + nA) * 64 + jc] = v;
            }
            if (nB < NN) {
                __half2 v = __floats2half2_rn(acc[mf][nf][2], acc[mf][nf][3]);
                *(__half2*)&dst[((size_t)t * NN + nB) * 64 + jc] = v;
            }
        }
    }
}

// ---------------- finalize: warp per (t, node), smem reduce over t ----------
#define FIN_NPB 2
__global__ void __launch_bounds__(320) k_finalize(const float* __restrict__ bias,
                                                  float* __restrict__ out) {
    __shared__ float red[FIN_NPB][T_STEPS][64];
    int tid = threadIdx.x;
    int wid = tid >> 5, lane = tid & 31;
    int slot = wid / T_STEPS;          // 0..1
    int t    = wid - slot * T_STEPS;   // 0..4
    int n = blockIdx.x * FIN_NPB + slot;

    if (n < NN) {
        int row = t * NN + n;
        int beg = g_rowptr[row];
        int c   = g_cnt[row];
        float2 a  = __half22float2(((const __half2*)(g_Ah + (size_t)row * 64))[lane]);
        float2 bi = *(const float2*)&bias[t * 64 + 2 * lane];
        float ax = a.x + bi.x, ay = a.y + bi.y;
        const __half2* Bt = (const __half2*)(g_Bh + (size_t)t * NN * 64);

        int dv = (lane < c) ? g_sdst[beg + lane] : 0;

        float sx = 0.f, sy = 0.f;
        int m = min(32, c);
        int i = 0;
        for (; i + 8 <= m; i += 8) {
            float2 bv[8];
            #pragma unroll
            for (int q = 0; q < 8; q++) {
                int dq = __shfl_sync(0xffffffffu, dv, i + q);
                bv[q] = __half22float2(Bt[(size_t)dq * 32 + lane]);
            }
            #pragma unroll
            for (int q = 0; q < 8; q++) {
                sx += fmaxf(ax + bv[q].x, 0.f);
                sy += fmaxf(ay + bv[q].y, 0.f);
            }
        }
        if (i + 4 <= m) {
            float2 bv[4];
            #pragma unroll
            for (int q = 0; q < 4; q++) {
                int dq = __shfl_sync(0xffffffffu, dv, i + q);
                bv[q] = __half22float2(Bt[(size_t)dq * 32 + lane]);
            }
            #pragma unroll
            for (int q = 0; q < 4; q++) {
                sx += fmaxf(ax + bv[q].x, 0.f);
                sy += fmaxf(ay + bv[q].y, 0.f);
            }
            i += 4;
        }
        for (; i < m; i++) {
            int di = __shfl_sync(0xffffffffu, dv, i);
            float2 bv = __half22float2(Bt[(size_t)di * 32 + lane]);
            sx += fmaxf(ax + bv.x, 0.f);
            sy += fmaxf(ay + bv.y, 0.f);
        }
        // rare tail: degree > 32
        for (int base = 32; base < c; base += 32) {
            int mm = min(32, c - base);
            int d = (lane < mm) ? g_sdst[beg + base + lane] : 0;
            for (int ii = 0; ii < mm; ii++) {
                int di = __shfl_sync(0xffffffffu, d, ii);
                float2 bv = __half22float2(Bt[(size_t)di * 32 + lane]);
                sx += fmaxf(ax + bv.x, 0.f);
                sy += fmaxf(ay + bv.y, 0.f);
            }
        }
        float scale = g_w[t] / (float)max(c, 1);
        red[slot][t][2 * lane]     = scale * sx;
        red[slot][t][2 * lane + 1] = scale * sy;
    }
    __syncthreads();

    if (tid < FIN_NPB * 64) {
        int s = tid >> 6, d = tid & 63;
        int n2 = blockIdx.x * FIN_NPB + s;
        if (n2 < NN) {
            float v = 0.f;
            #pragma unroll
            for (int tt = 0; tt < T_STEPS; tt++) v += red[s][tt][d];
            out[(size_t)n2 * 64 + d] = v;
        }
    }
}

// ---------------- launch: forked graph; k_gemm is launch #4 for ncu ---------
extern "C" void kernel_launch(void* const* d_in, const int* in_sizes, int n_in,
                              void* d_out, int out_size) {
    const float* x     = (const float*)d_in[0];  // (N, 64)
    const float* W     = (const float*)d_in[1];  // (T, 128, 64)
    const float* bias  = (const float*)d_in[2];  // (T, 64)
    const float* ea    = (const float*)d_in[3];  // (T,)
    const int*   edges = (const int*)d_in[4];    // (T, 2, E)
    float* out = (float*)d_out;

    (void)in_sizes; (void)n_in; (void)out_size;

    static cudaStream_t s2 = nullptr;
    static cudaEvent_t evFork = nullptr, evJoin = nullptr;
    static int gemm_smem = 3 * 128 * BS * sizeof(__half);  // 55296 B
    if (!s2) {
        cudaStreamCreateWithFlags(&s2, cudaStreamNonBlocking);
        cudaEventCreateWithFlags(&evFork, cudaEventDisableTiming);
        cudaEventCreateWithFlags(&evJoin, cudaEventDisableTiming);
        cudaFuncSetAttribute(k_gemm, cudaFuncAttributeMaxDynamicSharedMemorySize,
                             gemm_smem);
    }

    // fork point
    cudaEventRecord(evFork, 0);
    cudaStreamWaitEvent(s2, evFork, 0);

    dim3 egrid((EE + 255) / 256, T_STEPS);
    dim3 ggrid((NN + 127) / 128, T_STEPS);

    k_zero_cnt<<<(M_TOT + 255) / 256, 256, 0, s2>>>();        // #1 (edge, s2)
    k_softmax<<<1, 32>>>(ea);                                 // #2 (feat)
    k_split_xw<<<XSPLIT_BLOCKS + WSPLIT_BLOCKS, 256>>>(x, W); // #3 (feat)
    k_gemm<<<ggrid, 256, gemm_smem>>>();                      // #4 (feat) <- ncu

    k_hist<<<egrid, 256, 0, s2>>>(edges);
    k_scan1<<<NCHUNK, 256, 0, s2>>>();
    k_scan2<<<1, 512, 0, s2>>>();
    k_scan3<<<NCHUNK, 256, 0, s2>>>();
    k_scatter<<<egrid, 256, 0, s2>>>(edges);

    // join and finalize
    cudaEventRecord(evJoin, s2);
    cudaStreamWaitEvent(0, evJoin, 0);
    k_finalize<<<(NN + FIN_NPB - 1) / FIN_NPB, 320>>>(bias, out);
}